// round 14
// baseline (speedup 1.0000x reference)
#include <cuda_runtime.h>
#include <cuda_fp16.h>
#include <cstdint>

// Problem constants (fixed by the dataset)
#define B_  4
#define T_  2048
#define NH_ 8
#define N_  64
#define D_  128
#define C_  128          // chunk length
#define NC_ 16           // T_/C_
#define OUT_ELEMS (B_*T_*NH_*D_)   // 8,388,608
#define ST_ELEMS  (B_*NH_*N_*D_)   // 262,144

// Scratch:
//  g_dSh : per-chunk delta-state, fp16, layout [bh*16+k][d][n]
//  g_spf : prefix state (state + sum_{j<k} dS_j), fp16, [blk][d][n]
__device__ __half g_dSh[(size_t)512*8192];
__device__ __half g_spf[(size_t)512*8192];

// ---------------------------------------------------------------------------
// helpers
// ---------------------------------------------------------------------------
__device__ __forceinline__ uint32_t smem_u32(const void* p) {
    uint32_t a;
    asm("{ .reg .u64 t; cvta.to.shared.u64 t, %1; cvt.u32.u64 %0, t; }"
        : "=r"(a) : "l"(p));
    return a;
}
__device__ __forceinline__ void ldmx4(uint32_t* r, uint32_t a) {
    asm volatile("ldmatrix.sync.aligned.m8n8.x4.shared.b16 {%0,%1,%2,%3}, [%4];"
                 : "=r"(r[0]), "=r"(r[1]), "=r"(r[2]), "=r"(r[3]) : "r"(a));
}
__device__ __forceinline__ void ldmx4t(uint32_t* r, uint32_t a) {
    asm volatile("ldmatrix.sync.aligned.m8n8.x4.trans.shared.b16 {%0,%1,%2,%3}, [%4];"
                 : "=r"(r[0]), "=r"(r[1]), "=r"(r[2]), "=r"(r[3]) : "r"(a));
}
// D += A * B, m16n8k16, row.col, fp16 in / fp32 accum
__device__ __forceinline__ void mma(float* d, const uint32_t* a, const uint32_t* b) {
    asm volatile("mma.sync.aligned.m16n8k16.row.col.f32.f16.f16.f32 "
                 "{%0,%1,%2,%3}, {%4,%5,%6,%7}, {%8,%9}, {%0,%1,%2,%3};"
                 : "+f"(d[0]), "+f"(d[1]), "+f"(d[2]), "+f"(d[3])
                 : "r"(a[0]), "r"(a[1]), "r"(a[2]), "r"(a[3]),
                   "r"(b[0]), "r"(b[1]));
}
// pack two fp32 -> fp16x2 (a in low half)
__device__ __forceinline__ uint32_t pk2(float a, float b) {
    uint32_t r;
    asm("cvt.rn.f16x2.f32 %0, %1, %2;" : "=r"(r) : "f"(b), "f"(a));
    return r;
}

// padded row strides (fp16 elements): rows step 4 banks -> conflict-free ldmatrix
#define S64  72     // rows of 64 fp16
#define S128 136    // rows of 128 fp16

// ============================================================================
// Kernel A (2 heads per CTA, V + both Q tiles loaded up front, ONE sync):
//   dS^T[d][n] = sum_c V[c][d] * Q_h[c][n]  for h = hp*2, hp*2+1
// grid = 256 (b*64 + k*4 + hp), 512 threads, 2 CTAs/SM -> single wave
// ============================================================================
#define KA_SMEM ((size_t)(128*S128 + 2*128*S64)*2)   // 71,680 B

__global__ __launch_bounds__(512, 2) void kA(const float* __restrict__ Q,
                                             const float* __restrict__ V) {
    extern __shared__ __half sm[];
    __half* Vf = sm;                         // [128][S128]
    __half* Qf0 = Vf + 128 * S128;           // [128][S64] head 0
    __half* Qf1 = Qf0 + 128 * S64;           // [128][S64] head 1

    const int tid = threadIdx.x, w = tid >> 5, L = tid & 31;
    const int hp = blockIdx.x & 3, k = (blockIdx.x >> 2) & 15, b = blockIdx.x >> 6;

    const float* Vb = V + (size_t)(b * T_ + k * C_) * D_;
    const float* Qb0 = Q + ((size_t)(b * T_ + k * C_) * NH_ + hp * 2) * N_;

    // V natural [c][d]
#pragma unroll
    for (int it = 0; it < 8; it++) {
        int idx = tid + it * 512;                 // 4096 float4
        int d4 = idx & 31, c = idx >> 5;
        float4 v = *(const float4*)(Vb + (size_t)c * D_ + d4 * 4);
        *(uint2*)(Vf + c * S128 + d4 * 4) = make_uint2(pk2(v.x, v.y), pk2(v.z, v.w));
    }
    // Q natural [c][n], both heads (all LDGs overlap with V's)
#pragma unroll
    for (int hh = 0; hh < 2; hh++) {
        __half* Qf = hh ? Qf1 : Qf0;
        const float* Qb = Qb0 + (size_t)hh * N_;
#pragma unroll
        for (int it = 0; it < 4; it++) {
            int idx = tid + it * 512;             // 2048 float4
            int n4 = idx & 15, c = idx >> 4;
            float4 q = *(const float4*)(Qb + (size_t)c * (NH_ * N_) + n4 * 4);
            *(uint2*)(Qf + c * S64 + n4 * 4) = make_uint2(pk2(q.x, q.y), pk2(q.z, q.w));
        }
    }
    __syncthreads();                              // the ONLY sync

    const int wd = w & 7, nh = w >> 3;
    const uint32_t aA = smem_u32(
        Vf + ((L & 7) + ((L >> 4) << 3)) * S128 + 16 * wd + (((L >> 3) & 1) << 3));
    const uint32_t aB0 = smem_u32(Qf0 + (L & 15) * S64 + ((L >> 4) << 3) + nh * 32);
    const uint32_t QBUF = (uint32_t)(128 * S64 * 2);   // Qf0 -> Qf1 (bytes)

    const int r0d = 16 * wd + (L >> 2);
    const int cc = nh * 32 + (L & 3) * 2;

#pragma unroll
    for (int hh = 0; hh < 2; hh++) {
        const int h = hp * 2 + hh;
        const uint32_t aB = aB0 + hh * QBUF;

        float acc[4][4];
#pragma unroll
        for (int j = 0; j < 4; j++)
#pragma unroll
            for (int q = 0; q < 4; q++) acc[j][q] = 0.f;

#pragma unroll
        for (int kk = 0; kk < 8; kk++) {
            uint32_t a4[4];
            ldmx4t(a4, aA + kk * (16 * S128 * 2));
#pragma unroll
            for (int jp = 0; jp < 2; jp++) {
                uint32_t br[4];
                ldmx4t(br, aB + kk * (16 * S64 * 2) + jp * 32);
                mma(acc[2 * jp],     a4, br);
                mma(acc[2 * jp + 1], a4, br + 2);
            }
        }

        __half* op = g_dSh + (size_t)((b * NH_ + h) * NC_ + k) * 8192;
#pragma unroll
        for (int j = 0; j < 4; j++) {
            *(uint32_t*)(op + (size_t)r0d * 64 + 8 * j + cc)       = pk2(acc[j][0], acc[j][1]);
            *(uint32_t*)(op + (size_t)(r0d + 8) * 64 + 8 * j + cc) = pk2(acc[j][2], acc[j][3]);
        }
    }
}

// ============================================================================
// Kernel B (4-wide): exclusive prefix over the 16 chunks (fp16 dS) -> fp16
// prefix plane + fp32 new_state.  65536 threads, 4 consecutive n per thread.
// ============================================================================
__global__ void kB(const float* __restrict__ state, float* __restrict__ out_state) {
    int gid = blockIdx.x * 256 + threadIdx.x;       // < 65536
    int bh = gid >> 11;
    int e4 = (gid & 2047) * 4;
    int d = e4 >> 6, n0 = e4 & 63;
    const size_t base = (size_t)bh * NC_ * 8192 + e4;
    const size_t stb = ((size_t)bh * 64 + n0) * 128 + d;   // state[n][d], n stride 128

    float4 run;
    run.x = state[stb];
    run.y = state[stb + 128];
    run.z = state[stb + 256];
    run.w = state[stb + 384];
#pragma unroll
    for (int k = 0; k < NC_; k++) {
        uint2 dv = *(const uint2*)(g_dSh + base + (size_t)k * 8192);
        float2 f01 = __half22float2(*reinterpret_cast<__half2*>(&dv.x));
        float2 f23 = __half22float2(*reinterpret_cast<__half2*>(&dv.y));
        *(uint2*)(g_spf + base + (size_t)k * 8192) =
            make_uint2(pk2(run.x, run.y), pk2(run.z, run.w));
        run.x += f01.x; run.y += f01.y; run.z += f23.x; run.w += f23.y;
    }
    if (out_state) {
        out_state[stb]       = run.x;
        out_state[stb + 128] = run.y;
        out_state[stb + 256] = run.z;
        out_state[stb + 384] = run.w;
    }
}

// ============================================================================
// Kernel C (2 heads per CTA; V + both heads' Q and Spref loaded up front,
// ONE sync; per head: phase1 once, then per d-half phases 2+3):
//   rb = w<4 ? w : 11-w  (SMSP-balanced row blocks), triangular skip
// grid = 256 (b*64 + k*4 + hp), 256 threads, 2 CTAs/SM -> single wave
// ============================================================================
#define KC_SMEM ((size_t)(4*128*S64 + 128*S128)*2)   // 108,544 B

__global__ __launch_bounds__(256, 2) void kC(const float* __restrict__ Q,
                                             const float* __restrict__ V,
                                             float* __restrict__ out) {
    extern __shared__ __half sm[];
    __half* Qf0 = sm;                        // [128][S64]  Q[t][n] head 0
    __half* Qf1 = Qf0 + 128 * S64;           // head 1
    __half* Sf0 = Qf1 + 128 * S64;           // [128][S64]  Spref^T[d][n] head 0
    __half* Sf1 = Sf0 + 128 * S64;           // head 1
    __half* Vf  = Sf1 + 128 * S64;           // [128][S128] V[u][d]

    const int tid = threadIdx.x, w = tid >> 5, L = tid & 31;
    const int hp = blockIdx.x & 3, k = (blockIdx.x >> 2) & 15, b = blockIdx.x >> 6;

    const float* Vb = V + (size_t)(b * T_ + k * C_) * D_;
    const float* Qb0 = Q + ((size_t)(b * T_ + k * C_) * NH_ + hp * 2) * N_;

    // V natural [u][d]
#pragma unroll
    for (int it = 0; it < 16; it++) {
        int idx = tid + it * 256;                 // 4096 float4
        int d4 = idx & 31, u = idx >> 5;
        float4 v = *(const float4*)(Vb + (size_t)u * D_ + d4 * 4);
        *(uint2*)(Vf + u * S128 + d4 * 4) = make_uint2(pk2(v.x, v.y), pk2(v.z, v.w));
    }
    // Q + Spref for both heads (all loads overlap)
#pragma unroll
    for (int hh = 0; hh < 2; hh++) {
        __half* Qf = hh ? Qf1 : Qf0;
        __half* Sf = hh ? Sf1 : Sf0;
        const float* Qb = Qb0 + (size_t)hh * N_;
        const size_t cidx = (size_t)((b * NH_ + hp * 2 + hh) * NC_ + k);
#pragma unroll
        for (int it = 0; it < 8; it++) {
            int idx = tid + it * 256;             // 2048 float4
            int n4 = idx & 15, t = idx >> 4;
            float4 q = *(const float4*)(Qb + (size_t)t * (NH_ * N_) + n4 * 4);
            *(uint2*)(Qf + t * S64 + n4 * 4) = make_uint2(pk2(q.x, q.y), pk2(q.z, q.w));
        }
#pragma unroll
        for (int it = 0; it < 4; it++) {
            int idx = tid + it * 256;             // 1024 uint4
            int ch = idx & 7, d = idx >> 3;
            size_t sbase = cidx * 8192 + (size_t)d * 64 + ch * 8;
            *(uint4*)(Sf + d * S64 + ch * 8) = *(const uint4*)(g_spf + sbase);
        }
    }
    __syncthreads();                              // the ONLY sync

    // SMSP-balanced row-block permutation: pairs (0,7),(1,6),(2,5),(3,4)
    const int rb = (w < 4) ? w : 11 - w;
    const int Lm = L & 15;
    const uint32_t aQA0 = smem_u32(Qf0 + (16 * rb + Lm) * S64 + ((L >> 4) << 3));
    const uint32_t aQB0 = smem_u32(
        Qf0 + ((L & 7) + ((L >> 4) << 3)) * S64 + (((L >> 3) & 1) << 3));
    const uint32_t aSB0 = smem_u32(
        Sf0 + ((L & 7) + ((L >> 4) << 3)) * S64 + (((L >> 3) & 1) << 3));
    const uint32_t aVB = smem_u32(Vf + (L & 15) * S128 + ((L >> 4) << 3));
    const uint32_t QBUF = (uint32_t)(128 * S64 * 2);   // buffer step (bytes)

    const int r0 = 16 * rb + (L >> 2);
    const int tg = b * T_ + k * C_;

#pragma unroll
    for (int hh = 0; hh < 2; hh++) {
        const int h = hp * 2 + hh;
        const uint32_t aQA = aQA0 + hh * QBUF;
        const uint32_t aQB = aQB0 + hh * QBUF;
        const uint32_t aSB = aSB0 + hh * (2 * QBUF);   // Sf0 -> Sf1 skips Qf1+Sf0? no: layout Qf0,Qf1,Sf0,Sf1 -> Sf step = QBUF
        // NOTE: layout is Qf0,Qf1,Sf0,Sf1 so Sf1 = Sf0 + QBUF:
        const uint32_t aSBh = aSB0 + hh * QBUF;

        // A fragments for all 4 k16 blocks (n = 0..63): phases 1 and 2
        uint32_t Aall[4][4];
#pragma unroll
        for (int kk = 0; kk < 4; kk++) ldmx4(Aall[kk], aQA + kk * 32);

        // ---- Phase 1: scores = tril(Q Q^T, -1); PA[jp]: u = 16jp..16jp+15 ----
        uint32_t PA[8][4];
#pragma unroll
        for (int j = 0; j < 8; j++)
#pragma unroll
            for (int q = 0; q < 4; q++) PA[j][q] = 0u;

#pragma unroll
        for (int jp = 0; jp < 8; jp++) {
            if (jp <= rb) {                       // warp-uniform
                float sc0[4] = {0.f, 0.f, 0.f, 0.f};
                float sc1[4] = {0.f, 0.f, 0.f, 0.f};
#pragma unroll
                for (int kk = 0; kk < 4; kk++) {
                    uint32_t br[4];
                    ldmx4(br, aQB + jp * (16 * S64 * 2) + kk * 32);
                    mma(sc0, Aall[kk], br);
                    mma(sc1, Aall[kk], br + 2);
                }
                int u0 = 16 * jp + (L & 3) * 2;
                float x0 = (u0     < r0)     ? sc0[0] : 0.f;
                float x1 = (u0 + 1 < r0)     ? sc0[1] : 0.f;
                float x2 = (u0     < r0 + 8) ? sc0[2] : 0.f;
                float x3 = (u0 + 1 < r0 + 8) ? sc0[3] : 0.f;
                float y0 = (u0 + 8 < r0)     ? sc1[0] : 0.f;
                float y1 = (u0 + 9 < r0)     ? sc1[1] : 0.f;
                float y2 = (u0 + 8 < r0 + 8) ? sc1[2] : 0.f;
                float y3 = (u0 + 9 < r0 + 8) ? sc1[3] : 0.f;
                PA[jp][0] = pk2(x0, x1);
                PA[jp][1] = pk2(x2, x3);
                PA[jp][2] = pk2(y0, y1);
                PA[jp][3] = pk2(y2, y3);
            }
        }

        // ---- Per d-half: out = Q @ Spref + scores @ V ----
#pragma unroll
        for (int dh = 0; dh < 2; dh++) {
            const uint32_t sOff = (uint32_t)dh * (64 * S64 * 2);   // 64 d-rows
            const uint32_t vOff = (uint32_t)dh * 128;              // 64 d-cols (bytes)

            float o[8][4];
#pragma unroll
            for (int j = 0; j < 8; j++)
#pragma unroll
                for (int q = 0; q < 4; q++) o[j][q] = 0.f;

            // Phase 2: out = Q @ Spref_half (K = 64, 8 d-tiles)
#pragma unroll
            for (int kk = 0; kk < 4; kk++) {
#pragma unroll
                for (int jp = 0; jp < 4; jp++) {
                    uint32_t br[4];
                    ldmx4(br, aSBh + sOff + jp * (16 * S64 * 2) + kk * 32);
                    mma(o[2 * jp],     Aall[kk], br);
                    mma(o[2 * jp + 1], Aall[kk], br + 2);
                }
            }

            // Phase 3: out += scores @ V_half (kk <= rb, unrolled predication)
#pragma unroll
            for (int kk = 0; kk < 8; kk++) {
                if (kk <= rb) {                   // warp-uniform, static PA index
#pragma unroll
                    for (int jp = 0; jp < 4; jp++) {
                        uint32_t br[4];
                        ldmx4t(br, aVB + vOff + kk * (16 * S128 * 2) + jp * 32);
                        mma(o[2 * jp],     PA[kk], br);
                        mma(o[2 * jp + 1], PA[kk], br + 2);
                    }
                }
            }

            // store out[t][dh*64 + d-local]
#pragma unroll
            for (int j = 0; j < 8; j++) {
                int d0 = dh * 64 + 8 * j + (L & 3) * 2;
                *(float2*)(out + ((size_t)(tg + r0) * NH_ + h) * D_ + d0) =
                    make_float2(o[j][0], o[j][1]);
                *(float2*)(out + ((size_t)(tg + r0 + 8) * NH_ + h) * D_ + d0) =
                    make_float2(o[j][2], o[j][3]);
            }
        }
        (void)aSB;
    }
}

// ---------------------------------------------------------------------------
extern "C" void kernel_launch(void* const* d_in, const int* in_sizes, int n_in,
                              void* d_out, int out_size) {
    const float* Q     = (const float*)d_in[0];
    const float* V     = (const float*)d_in[1];
    const float* state = (const float*)d_in[2];
    float* out = (float*)d_out;

    cudaFuncSetAttribute(kA, cudaFuncAttributeMaxDynamicSharedMemorySize, (int)KA_SMEM);
    cudaFuncSetAttribute(kC, cudaFuncAttributeMaxDynamicSharedMemorySize, (int)KC_SMEM);

    bool write_state = (out_size >= (OUT_ELEMS + ST_ELEMS));
    float* out_state = write_state ? (out + OUT_ELEMS) : nullptr;

    kA<<<256, 512, KA_SMEM>>>(Q, V);
    kB<<<256, 256>>>(state, out_state);
    kC<<<256, 256, KC_SMEM>>>(Q, V, out);
}

// round 15
// speedup vs baseline: 1.0616x; 1.0616x over previous
#include <cuda_runtime.h>
#include <cuda_fp16.h>
#include <cstdint>

// Problem constants (fixed by the dataset)
#define B_  4
#define T_  2048
#define NH_ 8
#define N_  64
#define D_  128
#define C_  128          // chunk length
#define NC_ 16           // T_/C_
#define OUT_ELEMS (B_*T_*NH_*D_)   // 8,388,608
#define ST_ELEMS  (B_*NH_*N_*D_)   // 262,144

// Scratch:
//  g_dSh : per-chunk delta-state, fp16, layout [bh*16+k][d][n]
//  g_spf : prefix state (state + sum_{j<k} dS_j), fp16, [blk][d][n]
__device__ __half g_dSh[(size_t)512*8192];
__device__ __half g_spf[(size_t)512*8192];

// ---------------------------------------------------------------------------
// helpers
// ---------------------------------------------------------------------------
__device__ __forceinline__ uint32_t smem_u32(const void* p) {
    uint32_t a;
    asm("{ .reg .u64 t; cvta.to.shared.u64 t, %1; cvt.u32.u64 %0, t; }"
        : "=r"(a) : "l"(p));
    return a;
}
__device__ __forceinline__ void ldmx4(uint32_t* r, uint32_t a) {
    asm volatile("ldmatrix.sync.aligned.m8n8.x4.shared.b16 {%0,%1,%2,%3}, [%4];"
                 : "=r"(r[0]), "=r"(r[1]), "=r"(r[2]), "=r"(r[3]) : "r"(a));
}
__device__ __forceinline__ void ldmx4t(uint32_t* r, uint32_t a) {
    asm volatile("ldmatrix.sync.aligned.m8n8.x4.trans.shared.b16 {%0,%1,%2,%3}, [%4];"
                 : "=r"(r[0]), "=r"(r[1]), "=r"(r[2]), "=r"(r[3]) : "r"(a));
}
// D += A * B, m16n8k16, row.col, fp16 in / fp32 accum
__device__ __forceinline__ void mma(float* d, const uint32_t* a, const uint32_t* b) {
    asm volatile("mma.sync.aligned.m16n8k16.row.col.f32.f16.f16.f32 "
                 "{%0,%1,%2,%3}, {%4,%5,%6,%7}, {%8,%9}, {%0,%1,%2,%3};"
                 : "+f"(d[0]), "+f"(d[1]), "+f"(d[2]), "+f"(d[3])
                 : "r"(a[0]), "r"(a[1]), "r"(a[2]), "r"(a[3]),
                   "r"(b[0]), "r"(b[1]));
}
// pack two fp32 -> fp16x2 (a in low half)
__device__ __forceinline__ uint32_t pk2(float a, float b) {
    uint32_t r;
    asm("cvt.rn.f16x2.f32 %0, %1, %2;" : "=r"(r) : "f"(b), "f"(a));
    return r;
}

// padded row strides (fp16 elements): rows step 4 banks -> conflict-free ldmatrix
#define S64  72     // rows of 64 fp16
#define S128 136    // rows of 128 fp16

// ============================================================================
// Kernel A (2 heads per CTA, V loaded once; R13 phased-load structure):
//   dS^T[d][n] = sum_c V[c][d] * Q_h[c][n]  for h = hp*2, hp*2+1
// grid = 256 (b*64 + k*4 + hp), 512 threads, 2 CTAs/SM -> single wave
// ============================================================================
#define KA_SMEM ((size_t)(128*S128 + 128*S64)*2)   // 53,248 B

__global__ __launch_bounds__(512, 2) void kA(const float* __restrict__ Q,
                                             const float* __restrict__ V) {
    extern __shared__ __half sm[];
    __half* Vf = sm;                 // [128][S128]
    __half* Qf = Vf + 128 * S128;    // [128][S64]

    const int tid = threadIdx.x, w = tid >> 5, L = tid & 31;
    const int hp = blockIdx.x & 3, k = (blockIdx.x >> 2) & 15, b = blockIdx.x >> 6;

    const float* Vb = V + (size_t)(b * T_ + k * C_) * D_;

    // V natural [c][d] -- loaded ONCE for both heads
#pragma unroll
    for (int it = 0; it < 8; it++) {
        int idx = tid + it * 512;                 // 4096 float4
        int d4 = idx & 31, c = idx >> 5;
        float4 v = *(const float4*)(Vb + (size_t)c * D_ + d4 * 4);
        *(uint2*)(Vf + c * S128 + d4 * 4) = make_uint2(pk2(v.x, v.y), pk2(v.z, v.w));
    }

    const int wd = w & 7, nh = w >> 3;
    // A (V^T, m = d rows 16wd..16wd+15) trans x4
    const uint32_t aA = smem_u32(
        Vf + ((L & 7) + ((L >> 4) << 3)) * S128 + 16 * wd + (((L >> 3) & 1) << 3));
    // B (Q^T) trans x4: 16 n-cols per ldmatrix, base col = nh*32
    const uint32_t aB = smem_u32(Qf + (L & 15) * S64 + ((L >> 4) << 3) + nh * 32);

    const int r0d = 16 * wd + (L >> 2);
    const int cc = nh * 32 + (L & 3) * 2;

#pragma unroll
    for (int hh = 0; hh < 2; hh++) {
        const int h = hp * 2 + hh;
        const float* Qb = Q + ((size_t)(b * T_ + k * C_) * NH_ + h) * N_;

        // Q natural [c][n]
#pragma unroll
        for (int it = 0; it < 4; it++) {
            int idx = tid + it * 512;             // 2048 float4
            int n4 = idx & 15, c = idx >> 4;
            float4 q = *(const float4*)(Qb + (size_t)c * (NH_ * N_) + n4 * 4);
            *(uint2*)(Qf + c * S64 + n4 * 4) = make_uint2(pk2(q.x, q.y), pk2(q.z, q.w));
        }
        __syncthreads();

        float acc[4][4];
#pragma unroll
        for (int j = 0; j < 4; j++)
#pragma unroll
            for (int q = 0; q < 4; q++) acc[j][q] = 0.f;

#pragma unroll
        for (int kk = 0; kk < 8; kk++) {
            uint32_t a4[4];
            ldmx4t(a4, aA + kk * (16 * S128 * 2));
#pragma unroll
            for (int jp = 0; jp < 2; jp++) {
                uint32_t br[4];
                ldmx4t(br, aB + kk * (16 * S64 * 2) + jp * 32);
                mma(acc[2 * jp],     a4, br);
                mma(acc[2 * jp + 1], a4, br + 2);
            }
        }

        // fp16 dS store: each lane-quad writes a contiguous 16B segment per (j,row)
        __half* op = g_dSh + (size_t)((b * NH_ + h) * NC_ + k) * 8192;
#pragma unroll
        for (int j = 0; j < 4; j++) {
            *(uint32_t*)(op + (size_t)r0d * 64 + 8 * j + cc)       = pk2(acc[j][0], acc[j][1]);
            *(uint32_t*)(op + (size_t)(r0d + 8) * 64 + 8 * j + cc) = pk2(acc[j][2], acc[j][3]);
        }
        __syncthreads();   // Q buffer reused by next head
    }
}

// ============================================================================
// Kernel B (4-wide): exclusive prefix over the 16 chunks (fp16 dS) -> fp16
// prefix plane + fp32 new_state.  65536 threads, 4 consecutive n per thread.
// ============================================================================
__global__ void kB(const float* __restrict__ state, float* __restrict__ out_state) {
    int gid = blockIdx.x * 256 + threadIdx.x;       // < 65536
    int bh = gid >> 11;
    int e4 = (gid & 2047) * 4;
    int d = e4 >> 6, n0 = e4 & 63;
    const size_t base = (size_t)bh * NC_ * 8192 + e4;
    const size_t stb = ((size_t)bh * 64 + n0) * 128 + d;   // state[n][d], n stride 128

    float4 run;
    run.x = state[stb];
    run.y = state[stb + 128];
    run.z = state[stb + 256];
    run.w = state[stb + 384];
#pragma unroll
    for (int k = 0; k < NC_; k++) {
        uint2 dv = *(const uint2*)(g_dSh + base + (size_t)k * 8192);
        float2 f01 = __half22float2(*reinterpret_cast<__half2*>(&dv.x));
        float2 f23 = __half22float2(*reinterpret_cast<__half2*>(&dv.y));
        *(uint2*)(g_spf + base + (size_t)k * 8192) =
            make_uint2(pk2(run.x, run.y), pk2(run.z, run.w));
        run.x += f01.x; run.y += f01.y; run.z += f23.x; run.w += f23.y;
    }
    if (out_state) {
        out_state[stb]       = run.x;
        out_state[stb + 128] = run.y;
        out_state[stb + 256] = run.z;
        out_state[stb + 384] = run.w;
    }
}

// ============================================================================
// Kernel C (2 heads per CTA, V loaded once; R13 phased-load structure):
//   per head: scores = tril(Q Q^T, -1) once; out = Q @ Spref + scores @ V
//   rb = w<4 ? w : 11-w  (SMSP-balanced row blocks), triangular skip
// grid = 256 (b*64 + k*4 + hp), 256 threads, 2 CTAs/SM -> single wave
// ============================================================================
#define KC_SMEM ((size_t)(128*S64 + 128*S64 + 128*S128)*2)   // 71,680 B

__global__ __launch_bounds__(256, 2) void kC(const float* __restrict__ Q,
                                             const float* __restrict__ V,
                                             float* __restrict__ out) {
    extern __shared__ __half sm[];
    __half* Qf = sm;                 // [128][S64]   Q[t][n]
    __half* Sf = Qf + 128 * S64;     // [128][S64]   Spref^T[d][n] (full d)
    __half* Vf = Sf + 128 * S64;     // [128][S128]  V[u][d] (full d)

    const int tid = threadIdx.x, w = tid >> 5, L = tid & 31;
    const int hp = blockIdx.x & 3, k = (blockIdx.x >> 2) & 15, b = blockIdx.x >> 6;

    const float* Vb = V + (size_t)(b * T_ + k * C_) * D_;

    // V natural [u][d] -- loaded ONCE for both heads
#pragma unroll
    for (int it = 0; it < 16; it++) {
        int idx = tid + it * 256;                 // 4096 float4
        int d4 = idx & 31, u = idx >> 5;
        float4 v = *(const float4*)(Vb + (size_t)u * D_ + d4 * 4);
        *(uint2*)(Vf + u * S128 + d4 * 4) = make_uint2(pk2(v.x, v.y), pk2(v.z, v.w));
    }

    // SMSP-balanced row-block permutation: pairs (0,7),(1,6),(2,5),(3,4)
    const int rb = (w < 4) ? w : 11 - w;
    const int Lm = L & 15;
    const uint32_t aQA = smem_u32(Qf + (16 * rb + Lm) * S64 + ((L >> 4) << 3));
    const uint32_t aQB = smem_u32(
        Qf + ((L & 7) + ((L >> 4) << 3)) * S64 + (((L >> 3) & 1) << 3));
    const uint32_t aSB = smem_u32(
        Sf + ((L & 7) + ((L >> 4) << 3)) * S64 + (((L >> 3) & 1) << 3));
    const uint32_t aVB = smem_u32(Vf + (L & 15) * S128 + ((L >> 4) << 3));

    const int r0 = 16 * rb + (L >> 2);

#pragma unroll
    for (int hh = 0; hh < 2; hh++) {
        const int h = hp * 2 + hh;
        const float* Qb = Q + ((size_t)(b * T_ + k * C_) * NH_ + h) * N_;
        const size_t cidx = (size_t)((b * NH_ + h) * NC_ + k);

        // Q natural [t][n]
#pragma unroll
        for (int it = 0; it < 8; it++) {
            int idx = tid + it * 256;             // 2048 float4
            int n4 = idx & 15, t = idx >> 4;
            float4 q = *(const float4*)(Qb + (size_t)t * (NH_ * N_) + n4 * 4);
            *(uint2*)(Qf + t * S64 + n4 * 4) = make_uint2(pk2(q.x, q.y), pk2(q.z, q.w));
        }
        // Spref plane: straight 16B copies of [d][n] fp16 (all 128 d rows)
#pragma unroll
        for (int it = 0; it < 4; it++) {
            int idx = tid + it * 256;             // 1024 uint4
            int ch = idx & 7, d = idx >> 3;
            size_t sbase = cidx * 8192 + (size_t)d * 64 + ch * 8;
            *(uint4*)(Sf + d * S64 + ch * 8) = *(const uint4*)(g_spf + sbase);
        }
        __syncthreads();

        // A fragments for all 4 k16 blocks (n = 0..63): phases 1 and 2
        uint32_t Aall[4][4];
#pragma unroll
        for (int kk = 0; kk < 4; kk++) ldmx4(Aall[kk], aQA + kk * 32);

        // ---- Phase 1: scores = tril(Q Q^T, -1); PA[jp]: u = 16jp..16jp+15 ----
        uint32_t PA[8][4];
#pragma unroll
        for (int j = 0; j < 8; j++)
#pragma unroll
            for (int q = 0; q < 4; q++) PA[j][q] = 0u;

#pragma unroll
        for (int jp = 0; jp < 8; jp++) {
            if (jp <= rb) {                       // warp-uniform
                float sc0[4] = {0.f, 0.f, 0.f, 0.f};
                float sc1[4] = {0.f, 0.f, 0.f, 0.f};
#pragma unroll
                for (int kk = 0; kk < 4; kk++) {
                    uint32_t br[4];
                    ldmx4(br, aQB + jp * (16 * S64 * 2) + kk * 32);
                    mma(sc0, Aall[kk], br);
                    mma(sc1, Aall[kk], br + 2);
                }
                int u0 = 16 * jp + (L & 3) * 2;
                float x0 = (u0     < r0)     ? sc0[0] : 0.f;
                float x1 = (u0 + 1 < r0)     ? sc0[1] : 0.f;
                float x2 = (u0     < r0 + 8) ? sc0[2] : 0.f;
                float x3 = (u0 + 1 < r0 + 8) ? sc0[3] : 0.f;
                float y0 = (u0 + 8 < r0)     ? sc1[0] : 0.f;
                float y1 = (u0 + 9 < r0)     ? sc1[1] : 0.f;
                float y2 = (u0 + 8 < r0 + 8) ? sc1[2] : 0.f;
                float y3 = (u0 + 9 < r0 + 8) ? sc1[3] : 0.f;
                PA[jp][0] = pk2(x0, x1);
                PA[jp][1] = pk2(x2, x3);
                PA[jp][2] = pk2(y0, y1);
                PA[jp][3] = pk2(y2, y3);
            }
        }

        // ---- Per d-half: out = Q @ Spref + scores @ V ----
        const int tg = b * T_ + k * C_;
#pragma unroll
        for (int dh = 0; dh < 2; dh++) {
            const uint32_t sOff = (uint32_t)dh * (64 * S64 * 2);   // 64 d-rows
            const uint32_t vOff = (uint32_t)dh * 128;              // 64 d-cols (bytes)

            float o[8][4];
#pragma unroll
            for (int j = 0; j < 8; j++)
#pragma unroll
                for (int q = 0; q < 4; q++) o[j][q] = 0.f;

            // Phase 2: out = Q @ Spref_half (K = 64, 8 d-tiles)
#pragma unroll
            for (int kk = 0; kk < 4; kk++) {
#pragma unroll
                for (int jp = 0; jp < 4; jp++) {
                    uint32_t br[4];
                    ldmx4(br, aSB + sOff + jp * (16 * S64 * 2) + kk * 32);
                    mma(o[2 * jp],     Aall[kk], br);
                    mma(o[2 * jp + 1], Aall[kk], br + 2);
                }
            }

            // Phase 3: out += scores @ V_half (kk <= rb, unrolled predication)
#pragma unroll
            for (int kk = 0; kk < 8; kk++) {
                if (kk <= rb) {                   // warp-uniform, static PA index
#pragma unroll
                    for (int jp = 0; jp < 4; jp++) {
                        uint32_t br[4];
                        ldmx4t(br, aVB + vOff + kk * (16 * S128 * 2) + jp * 32);
                        mma(o[2 * jp],     PA[kk], br);
                        mma(o[2 * jp + 1], PA[kk], br + 2);
                    }
                }
            }

            // store out[t][dh*64 + d-local]
#pragma unroll
            for (int j = 0; j < 8; j++) {
                int d0 = dh * 64 + 8 * j + (L & 3) * 2;
                *(float2*)(out + ((size_t)(tg + r0) * NH_ + h) * D_ + d0) =
                    make_float2(o[j][0], o[j][1]);
                *(float2*)(out + ((size_t)(tg + r0 + 8) * NH_ + h) * D_ + d0) =
                    make_float2(o[j][2], o[j][3]);
            }
        }
        __syncthreads();   // Qf/Sf reused by next head
    }
}

// ---------------------------------------------------------------------------
extern "C" void kernel_launch(void* const* d_in, const int* in_sizes, int n_in,
                              void* d_out, int out_size) {
    const float* Q     = (const float*)d_in[0];
    const float* V     = (const float*)d_in[1];
    const float* state = (const float*)d_in[2];
    float* out = (float*)d_out;

    cudaFuncSetAttribute(kA, cudaFuncAttributeMaxDynamicSharedMemorySize, (int)KA_SMEM);
    cudaFuncSetAttribute(kC, cudaFuncAttributeMaxDynamicSharedMemorySize, (int)KC_SMEM);

    bool write_state = (out_size >= (OUT_ELEMS + ST_ELEMS));
    float* out_state = write_state ? (out + OUT_ELEMS) : nullptr;

    kA<<<256, 512, KA_SMEM>>>(Q, V);
    kB<<<256, 256>>>(state, out_state);
    kC<<<256, 256, KC_SMEM>>>(Q, V, out);
}